// round 14
// baseline (speedup 1.0000x reference)
#include <cuda_runtime.h>
#include <cuda_bf16.h>
#include <cuda_fp16.h>
#include <cstdint>

#define D   4096
#define BSR 4096
#define SEQ 1024
#define NH  32
#define HD  128
#define LR  16
#define SCALE 0.08838834764831845f

// ------------------------- device scratch ---------------------------------
__device__ __half g_xh[(size_t)BSR * D], g_xl[(size_t)BSR * D];
__device__ __half g_Wq[(size_t)D * D], g_Wk[(size_t)D * D];
__device__ __half g_Wv[(size_t)D * D], g_Wo[(size_t)D * D];
__device__ __half g_Q[(size_t)BSR * D], g_K[(size_t)BSR * D], g_V[(size_t)BSR * D];
__device__ __half g_Oh[(size_t)BSR * D], g_Ol[(size_t)BSR * D];

// ------------------------- PTX helpers (base-target only) ------------------
__device__ __forceinline__ uint32_t smem_to_u32(const void* p) {
    uint32_t a;
    asm("{ .reg .u64 t; cvta.to.shared.u64 t, %1; cvt.u32.u64 %0, t; }"
        : "=r"(a) : "l"(p));
    return a;
}
#define CP16(dst, src) \
    asm volatile("cp.async.cg.shared.global [%0], [%1], 16;" \
                 :: "r"(dst), "l"(src))
#define CP_COMMIT() asm volatile("cp.async.commit_group;" ::: "memory")
#define CP_WAIT1()  asm volatile("cp.async.wait_group 1;" ::: "memory")
#define CP_WAIT0()  asm volatile("cp.async.wait_group 0;" ::: "memory")

#define LDSM4(r0, r1, r2, r3, addr) \
    asm volatile("ldmatrix.sync.aligned.m8n8.x4.shared.b16 {%0,%1,%2,%3}, [%4];" \
                 : "=r"(r0), "=r"(r1), "=r"(r2), "=r"(r3) : "r"(addr))
#define LDSM4T(r0, r1, r2, r3, addr) \
    asm volatile("ldmatrix.sync.aligned.m8n8.x4.trans.shared.b16 {%0,%1,%2,%3}, [%4];" \
                 : "=r"(r0), "=r"(r1), "=r"(r2), "=r"(r3) : "r"(addr))
#define LDSM2(r0, r1, addr) \
    asm volatile("ldmatrix.sync.aligned.m8n8.x2.shared.b16 {%0,%1}, [%2];" \
                 : "=r"(r0), "=r"(r1) : "r"(addr))
#define MMAF16(c, a0, a1, a2, a3, b0, b1) \
    asm volatile("mma.sync.aligned.m16n8k16.row.col.f32.f16.f16.f32 " \
                 "{%0,%1,%2,%3}, {%4,%5,%6,%7}, {%8,%9}, {%0,%1,%2,%3};" \
                 : "+f"((c)[0]), "+f"((c)[1]), "+f"((c)[2]), "+f"((c)[3]) \
                 : "r"(a0), "r"(a1), "r"(a2), "r"(a3), "r"(b0), "r"(b1))

// ------------------------- fused prep kernels ------------------------------
// LoRA merge -> fp16 weights, 4 elements/thread (float4 A rows).
__global__ void prep_merge(const float* __restrict__ wq_w,
                           const float* __restrict__ wq_a,
                           const float* __restrict__ wq_b,
                           const float* __restrict__ wv_w,
                           const float* __restrict__ wv_a,
                           const float* __restrict__ wv_b,
                           __half* __restrict__ Wq,
                           __half* __restrict__ Wv) {
    const int sel = blockIdx.x >> 14;            // 16384 blocks per matrix
    const int idx = (((blockIdx.x & 16383) << 8) + threadIdx.x) * 4;
    const float* w = sel ? wv_w : wq_w;
    const float* a = sel ? wv_a : wq_a;
    const float* b = sel ? wv_b : wq_b;
    __half* o      = sel ? Wv   : Wq;
    const int n = idx >> 12, k = idx & (D - 1);
    float4 acc = *(const float4*)(w + idx);
#pragma unroll
    for (int r = 0; r < LR; r++) {
        const float bv = 2.0f * __ldg(&b[n * LR + r]);
        const float4 av = *(const float4*)(a + r * D + k);
        acc.x += bv * av.x; acc.y += bv * av.y;
        acc.z += bv * av.z; acc.w += bv * av.w;
    }
    __half h[4];
    h[0] = __float2half_rn(acc.x); h[1] = __float2half_rn(acc.y);
    h[2] = __float2half_rn(acc.z); h[3] = __float2half_rn(acc.w);
    *(float2*)(o + idx) = *(float2*)h;
}

__global__ void prep_split(const float* __restrict__ wk_w,
                           const float* __restrict__ wo_w,
                           const float* __restrict__ x,
                           __half* __restrict__ Wk,
                           __half* __restrict__ Wo,
                           __half* __restrict__ xh,
                           __half* __restrict__ xl) {
    const int sel = blockIdx.x >> 13;
    const size_t i = (((size_t)(blockIdx.x & 8191) << 8) + threadIdx.x) * 8;
    const float* src = sel == 0 ? wk_w : (sel == 1 ? wo_w : x);
    float v[8];
    *(float4*)&v[0] = *(const float4*)(src + i);
    *(float4*)&v[4] = *(const float4*)(src + i + 4);
    __half h[8];
#pragma unroll
    for (int j = 0; j < 8; j++) h[j] = __float2half_rn(v[j]);
    if (sel == 2) {
        __half l[8];
#pragma unroll
        for (int j = 0; j < 8; j++)
            l[j] = __float2half_rn(v[j] - __half2float(h[j]));
        *(float4*)(xh + i) = *(float4*)h;
        *(float4*)(xl + i) = *(float4*)l;
    } else {
        __half* dst = sel == 0 ? Wk : Wo;
        *(float4*)(dst + i) = *(float4*)h;
    }
}

// ------------- fp16 2-term GEMM (NT), 2 CTAs/SM ----------------------------
// C = Ah*B^T + Al*B^T. BM=BN=128, BK=64, 256 thr. 2 stages, 96KB/CTA.
// MODE 0: single output (fp32 C) — O projection.  Grid (32, 32, 1).
// MODE 1: fused QKV — blockIdx.z selects B/out/epilogue:
//         z=0: Q = RoPE+scale -> fp16; z=1: K = RoPE -> fp16; z=2: V -> fp16.
#define GTILE   16384
#define GSTAGE  (3 * GTILE)
#define GEMM_SMEM (2 * GSTAGE)
#define NCHUNK  64   // D / BK

template <int MODE>
__global__ void __launch_bounds__(256, 2) gemm16(
    const __half* __restrict__ Ah, const __half* __restrict__ Al,
    const __half* __restrict__ B0, const __half* __restrict__ B1,
    const __half* __restrict__ B2,
    float* __restrict__ C,
    __half* __restrict__ O0, __half* __restrict__ O1, __half* __restrict__ O2,
    const float* __restrict__ fc, const float* __restrict__ fs) {
    extern __shared__ char smch[];
    const uint32_t smb = smem_to_u32(smch);
    const int tid = threadIdx.x, lane = tid & 31, wid = tid >> 5;
    const int warp_m = wid & 1;
    const int warp_n = wid >> 1;
    const int bm = blockIdx.y * 128, bn = blockIdx.x * 128;
    const int z = blockIdx.z;
    const __half* B = (MODE == 0) ? B0 : (z == 0 ? B0 : (z == 1 ? B1 : B2));

    float acc[4][4][4];
#pragma unroll
    for (int i = 0; i < 4; i++)
#pragma unroll
        for (int j = 0; j < 4; j++)
#pragma unroll
            for (int k = 0; k < 4; k++) acc[i][j][k] = 0.0f;

    const int r0 = tid >> 3, c0 = tid & 7;
    const uint32_t dst0 = r0 * 128 + (uint32_t)((c0 ^ (r0 & 7)) * 16);
    const __half* gAh = Ah + ((size_t)(bm + r0) << 12) + c0 * 8;
    const __half* gAl = Al + ((size_t)(bm + r0) << 12) + c0 * 8;
    const __half* gB  = B  + ((size_t)(bn + r0) << 12) + c0 * 8;

#define ISSUE(ck, st) do {                                                     \
        const uint32_t sb_ = smb + (st) * GSTAGE + dst0;                       \
        const size_t go_ = (size_t)(ck) * 64;                                  \
        _Pragma("unroll")                                                      \
        for (int j = 0; j < 4; j++) {                                          \
            const uint32_t d_ = sb_ + j * 32 * 128;                            \
            const size_t s_ = go_ + ((size_t)j << 17);                         \
            CP16(d_,             (const char*)(gAh + s_));                     \
            CP16(d_ + GTILE,     (const char*)(gAl + s_));                     \
            CP16(d_ + 2 * GTILE, (const char*)(gB  + s_));                     \
        }                                                                      \
        CP_COMMIT();                                                           \
    } while (0)

    ISSUE(0, 0);
    ISSUE(1, 1);

    const int arow = warp_m * 64 + (lane & 15);
    const int akh  = lane >> 4;
    const int brow = warp_n * 32 + (lane & 7);
    const int bkh  = (lane >> 3) & 1;

    for (int ck = 0; ck < NCHUNK; ck++) {
        const int st = ck & 1;
        if (ck + 2 >= NCHUNK) { CP_WAIT0(); } else { CP_WAIT1(); }
        __syncthreads();

        const uint32_t sAh = smb + st * GSTAGE;
        const uint32_t sAl = sAh + GTILE;
        const uint32_t sB  = sAh + 2 * GTILE;

#pragma unroll
        for (int ks = 0; ks < 4; ks++) {
            uint32_t bb[4][2];
#pragma unroll
            for (int nt = 0; nt < 4; nt++) {
                const int r = brow + nt * 8;
                const uint32_t adr = r * 128 + (((ks * 2 + bkh) ^ (r & 7)) * 16);
                LDSM2(bb[nt][0], bb[nt][1], sB + adr);
            }
#pragma unroll
            for (int mt = 0; mt < 4; mt++) {
                const int r = arow + mt * 16;
                const uint32_t adr = r * 128 + (((ks * 2 + akh) ^ (r & 7)) * 16);
                uint32_t a0, a1, a2, a3;
                LDSM4(a0, a1, a2, a3, sAh + adr);
#pragma unroll
                for (int nt = 0; nt < 4; nt++)
                    MMAF16(acc[mt][nt], a0, a1, a2, a3, bb[nt][0], bb[nt][1]);
                LDSM4(a0, a1, a2, a3, sAl + adr);
#pragma unroll
                for (int nt = 0; nt < 4; nt++)
                    MMAF16(acc[mt][nt], a0, a1, a2, a3, bb[nt][0], bb[nt][1]);
            }
        }
        __syncthreads();
        if (ck + 2 < NCHUNK) ISSUE(ck + 2, st);
    }

    // epilogue
    __half* outp = (MODE == 1) ? (z == 0 ? O0 : (z == 1 ? O1 : O2)) : (__half*)0;
    const bool doRope  = (MODE == 1) && (z < 2);
    const bool doScale = (MODE == 1) && (z == 0);
#pragma unroll
    for (int mt = 0; mt < 4; mt++) {
        const int row = bm + warp_m * 64 + mt * 16 + (lane >> 2);
#pragma unroll
        for (int nt = 0; nt < 4; nt++) {
            const int col = bn + warp_n * 32 + nt * 8 + (lane & 3) * 2;
            float v0 = acc[mt][nt][0], v1 = acc[mt][nt][1];
            float v2 = acc[mt][nt][2], v3 = acc[mt][nt][3];
            if (doRope) {
                const int i = (col & (HD - 1)) >> 1;
                const int s1 = row & (SEQ - 1);
                const int s2 = (row + 8) & (SEQ - 1);
                const float c1 = __ldg(&fc[s1 * 64 + i]), n1 = __ldg(&fs[s1 * 64 + i]);
                const float c2 = __ldg(&fc[s2 * 64 + i]), n2 = __ldg(&fs[s2 * 64 + i]);
                float t;
                t  = v0 * c1 - v1 * n1; v1 = v0 * n1 + v1 * c1; v0 = t;
                t  = v2 * c2 - v3 * n2; v3 = v2 * n2 + v3 * c2; v2 = t;
            }
            if (doScale) { v0 *= SCALE; v1 *= SCALE; v2 *= SCALE; v3 *= SCALE; }
            if (MODE == 0) {
                *(float2*)&C[(size_t)row * D + col]       = make_float2(v0, v1);
                *(float2*)&C[(size_t)(row + 8) * D + col] = make_float2(v2, v3);
            } else {
                __half2 p; p.x = __float2half_rn(v0); p.y = __float2half_rn(v1);
                *(__half2*)&outp[(size_t)row * D + col] = p;
                __half2 q; q.x = __float2half_rn(v2); q.y = __float2half_rn(v3);
                *(__half2*)&outp[(size_t)(row + 8) * D + col] = q;
            }
        }
    }
}

// ---------------- MMA flash attention (fp16 1-term, causal) ----------------
// BM=64, 128 threads (4 warps x 16 q-rows), 2 CTAs/SM for cross-CTA overlap
// of the serial softmax chain with the other CTA's MMAs.
// Grid (16, NH, B); qt = 15 - bx (largest diagonals scheduled first).
// Q tile 64x128 fp16 (16KB); K/V tiles 64x128 fp16 double-buffered (32KB/st).
// Per-warp math identical to R13 -> bitwise-identical output.
#define AT_Q    0
#define AT_ST   16384
#define AT_STSZ 32768   // K 16KB | V 16KB
#define ATTN_SMEM (AT_ST + 2 * AT_STSZ)

__global__ void __launch_bounds__(128, 2) attn_mma() {
    extern __shared__ char smc[];
    const uint32_t smb = smem_to_u32(smc);
    const int b = blockIdx.z, h = blockIdx.y;
    const int qt = (SEQ / 64 - 1) - blockIdx.x;   // largest-first
    const int q0 = qt * 64;
    const int tid = threadIdx.x, lane = tid & 31, wid = tid >> 5;

    const size_t qoff = ((size_t)(b * SEQ + q0) << 12) + (size_t)h * HD;
    const size_t koff = ((size_t)(b * SEQ) << 12) + (size_t)h * HD;

    // Q load: 64 rows x 16 chunks = 1024 chunks, 8 per thread
#pragma unroll
    for (int j = 0; j < 8; j++) {
        int q = tid + 128 * j;
        int r = q >> 4, dt = q & 15;
        int srow = 2 * r + (dt >> 3);
        uint32_t adr = srow * 128 + (uint32_t)((((dt & 7)) ^ (srow & 7)) * 16);
        CP16(smb + AT_Q + adr, (const char*)(g_Q + qoff + ((size_t)r << 12) + dt * 8));
    }

#define ISSUE_KV(kt, st) do {                                                  \
        const size_t kb_ = koff + ((size_t)((kt) * 64) << 12);                 \
        const uint32_t sb_ = smb + AT_ST + (st) * AT_STSZ;                     \
        _Pragma("unroll")                                                      \
        for (int j = 0; j < 8; j++) {                                          \
            int q_ = tid + 128 * j;                                            \
            int r_ = q_ >> 4, dt_ = q_ & 15;                                   \
            int sr_ = 2 * r_ + (dt_ >> 3);                                     \
            uint32_t ad_ = sr_ * 128 + (uint32_t)(((dt_ & 7) ^ (sr_ & 7)) * 16); \
            const size_t g_ = kb_ + ((size_t)r_ << 12) + dt_ * 8;              \
            CP16(sb_ + ad_,         (const char*)(g_K + g_));                  \
            CP16(sb_ + 16384 + ad_, (const char*)(g_V + g_));                  \
        }                                                                      \
        CP_COMMIT();                                                           \
    } while (0)

    ISSUE_KV(0, 0);

    float o[16][4];
#pragma unroll
    for (int i = 0; i < 16; i++)
#pragma unroll
        for (int j = 0; j < 4; j++) o[i][j] = 0.0f;
    float m[2] = {-1e30f, -1e30f}, lsum[2] = {0.0f, 0.0f};

    const int ktiles = qt + 1;
    const int ar = wid * 16 + (lane & 15);
    const int akh = lane >> 4;

    for (int kt = 0; kt < ktiles; kt++) {
        const int st = kt & 1;
        if (kt + 1 < ktiles) { ISSUE_KV(kt + 1, st ^ 1); CP_WAIT1(); }
        else                 { CP_WAIT0(); }
        __syncthreads();

        const uint32_t sQ = smb + AT_Q;
        const uint32_t sK = smb + AT_ST + st * AT_STSZ;
        const uint32_t sV = sK + 16384;

        // ---- S = Q K^T (1-term fp16) ----
        float sc[8][4];
#pragma unroll
        for (int t = 0; t < 8; t++)
#pragma unroll
            for (int j = 0; j < 4; j++) sc[t][j] = 0.0f;

#pragma unroll
        for (int ks = 0; ks < 8; ks++) {
            const int qs = 2 * ar + (ks >> 2);
            const uint32_t aadr = qs * 128 +
                (uint32_t)(((((ks & 3) * 2 + akh)) ^ (qs & 7)) * 16);
            uint32_t qf[4];
            LDSM4(qf[0], qf[1], qf[2], qf[3], sQ + aadr);
#pragma unroll
            for (int ntp = 0; ntp < 4; ntp++) {
                const int kr = ((lane >> 4) ? (2 * ntp + 1) : (2 * ntp)) * 8 + (lane & 7);
                const int kkh = (lane >> 3) & 1;
                const int ksr = 2 * kr + (ks >> 2);
                const uint32_t kadr = ksr * 128 +
                    (uint32_t)(((((ks & 3) * 2 + kkh)) ^ (ksr & 7)) * 16);
                uint32_t kf[4];
                LDSM4(kf[0], kf[1], kf[2], kf[3], sK + kadr);
                MMAF16(sc[2*ntp],   qf[0], qf[1], qf[2], qf[3], kf[0], kf[1]);
                MMAF16(sc[2*ntp+1], qf[0], qf[1], qf[2], qf[3], kf[2], kf[3]);
            }
        }

        // ---- causal mask (only on diagonal tile kt == qt) ----
        const int k0 = kt * 64;
        if (k0 + 63 > q0) {
            const int rb = q0 + wid * 16 + (lane >> 2);
#pragma unroll
            for (int t = 0; t < 8; t++) {
                const int cb = k0 + t * 8 + (lane & 3) * 2;
                if (cb     > rb)     sc[t][0] = -1e30f;
                if (cb + 1 > rb)     sc[t][1] = -1e30f;
                if (cb     > rb + 8) sc[t][2] = -1e30f;
                if (cb + 1 > rb + 8) sc[t][3] = -1e30f;
            }
        }

        // ---- online softmax ----
#pragma unroll
        for (int rh = 0; rh < 2; rh++) {
            float mx = -1e30f;
#pragma unroll
            for (int t = 0; t < 8; t++)
                mx = fmaxf(mx, fmaxf(sc[t][2*rh], sc[t][2*rh+1]));
            mx = fmaxf(mx, __shfl_xor_sync(0xffffffffu, mx, 1));
            mx = fmaxf(mx, __shfl_xor_sync(0xffffffffu, mx, 2));
            const float mnew = fmaxf(m[rh], mx);
            const float alpha = __expf(m[rh] - mnew);
            float s = 0.0f;
#pragma unroll
            for (int t = 0; t < 8; t++) {
                float p0 = __expf(sc[t][2*rh]   - mnew);
                float p1 = __expf(sc[t][2*rh+1] - mnew);
                sc[t][2*rh] = p0; sc[t][2*rh+1] = p1;
                s += p0 + p1;
            }
            s += __shfl_xor_sync(0xffffffffu, s, 1);
            s += __shfl_xor_sync(0xffffffffu, s, 2);
            lsum[rh] = lsum[rh] * alpha + s;
            m[rh] = mnew;
#pragma unroll
            for (int dt = 0; dt < 16; dt++) {
                o[dt][2*rh]   *= alpha;
                o[dt][2*rh+1] *= alpha;
            }
        }

        // ---- O += P V (1-term fp16) ----
#pragma unroll
        for (int kj = 0; kj < 4; kj++) {
            uint32_t ph[4];
#pragma unroll
            for (int u = 0; u < 4; u++) {
                const float* sp = sc[2 * kj + (u >> 1)];
                __half2 hp;
                hp.x = __float2half_rn(sp[(u & 1) * 2]);
                hp.y = __float2half_rn(sp[(u & 1) * 2 + 1]);
                ph[u] = *(uint32_t*)&hp;
            }
            const int jr = kj * 16 + (lane & 7) + (((lane >> 3) & 1) << 3);
#pragma unroll
            for (int npp = 0; npp < 4; npp++) {
                const int np0 = 2 * npp, np1 = 2 * npp + 1;
                uint32_t vA[4], vB[4];
                {
                    const int dtc = 2 * np0 + (lane >> 4);
                    const int vsr = 2 * jr + (dtc >> 3);
                    const uint32_t vadr = vsr * 128 +
                        (uint32_t)((((dtc & 7)) ^ (vsr & 7)) * 16);
                    LDSM4T(vA[0], vA[1], vA[2], vA[3], sV + vadr);
                }
                {
                    const int dtc = 2 * np1 + (lane >> 4);
                    const int vsr = 2 * jr + (dtc >> 3);
                    const uint32_t vadr = vsr * 128 +
                        (uint32_t)((((dtc & 7)) ^ (vsr & 7)) * 16);
                    LDSM4T(vB[0], vB[1], vB[2], vB[3], sV + vadr);
                }
                MMAF16(o[2*np0],   ph[0], ph[1], ph[2], ph[3], vA[0], vA[1]);
                MMAF16(o[2*np0+1], ph[0], ph[1], ph[2], ph[3], vA[2], vA[3]);
                MMAF16(o[2*np1],   ph[0], ph[1], ph[2], ph[3], vB[0], vB[1]);
                MMAF16(o[2*np1+1], ph[0], ph[1], ph[2], ph[3], vB[2], vB[3]);
            }
        }
        __syncthreads();
    }

    // ---- epilogue: normalize + fp16 hi/lo split (feeds 2-term O-GEMM) ----
#pragma unroll
    for (int rh = 0; rh < 2; rh++) {
        const float inv = 1.0f / lsum[rh];
        const int row = q0 + wid * 16 + (lane >> 2) + rh * 8;
        const size_t ro = ((size_t)(b * SEQ + row) << 12) + (size_t)h * HD
                          + (lane & 3) * 2;
#pragma unroll
        for (int dt = 0; dt < 16; dt++) {
            const float v0 = o[dt][2*rh] * inv, v1 = o[dt][2*rh+1] * inv;
            __half h0 = __float2half_rn(v0), h1 = __float2half_rn(v1);
            __half2 hp; hp.x = h0; hp.y = h1;
            *(__half2*)&g_Oh[ro + dt * 8] = hp;
            __half2 lp;
            lp.x = __float2half_rn(v0 - __half2float(h0));
            lp.y = __float2half_rn(v1 - __half2float(h1));
            *(__half2*)&g_Ol[ro + dt * 8] = lp;
        }
    }
}

// ---------------- launcher -------------------------------------------------
extern "C" void kernel_launch(void* const* d_in, const int* in_sizes, int n_in,
                              void* d_out, int out_size) {
    const float* x    = (const float*)d_in[0];
    const float* wq_w = (const float*)d_in[1];
    const float* wq_a = (const float*)d_in[2];
    const float* wq_b = (const float*)d_in[3];
    const float* wk_w = (const float*)d_in[4];
    const float* wv_w = (const float*)d_in[5];
    const float* wv_a = (const float*)d_in[6];
    const float* wv_b = (const float*)d_in[7];
    const float* wo_w = (const float*)d_in[8];
    const float* fc   = (const float*)d_in[9];
    const float* fs   = (const float*)d_in[10];
    float* out = (float*)d_out;

    __half *xh, *xl, *Wq, *Wk, *Wv, *Wo, *Q, *K, *V, *Oh, *Ol;
    cudaGetSymbolAddress((void**)&xh, g_xh); cudaGetSymbolAddress((void**)&xl, g_xl);
    cudaGetSymbolAddress((void**)&Wq, g_Wq); cudaGetSymbolAddress((void**)&Wk, g_Wk);
    cudaGetSymbolAddress((void**)&Wv, g_Wv); cudaGetSymbolAddress((void**)&Wo, g_Wo);
    cudaGetSymbolAddress((void**)&Q, g_Q);   cudaGetSymbolAddress((void**)&K, g_K);
    cudaGetSymbolAddress((void**)&V, g_V);
    cudaGetSymbolAddress((void**)&Oh, g_Oh); cudaGetSymbolAddress((void**)&Ol, g_Ol);

    cudaFuncSetAttribute(gemm16<0>, cudaFuncAttributeMaxDynamicSharedMemorySize, GEMM_SMEM);
    cudaFuncSetAttribute(gemm16<1>, cudaFuncAttributeMaxDynamicSharedMemorySize, GEMM_SMEM);
    cudaFuncSetAttribute(attn_mma, cudaFuncAttributeMaxDynamicSharedMemorySize, ATTN_SMEM);

    // 1) fused prep
    prep_merge<<<2 * 16384, 256>>>(wq_w, wq_a, wq_b, wv_w, wv_a, wv_b, Wq, Wv);
    prep_split<<<3 * 8192, 256>>>(wk_w, wo_w, x, Wk, Wo, xh, xl);

    // 2) fused QKV projection (one launch, 3072 tiles)
    gemm16<1><<<dim3(D / 128, BSR / 128, 3), 256, GEMM_SMEM>>>(
        xh, xl, Wq, Wk, Wv, nullptr, Q, K, V, fc, fs);

    // 3) fp16 1-term MMA flash attention (BM=64, 2 CTAs/SM, largest-first)
    attn_mma<<<dim3(SEQ / 64, NH, 4), 128, ATTN_SMEM>>>();

    // 4) output projection (fp16 2-term, fp32 out)
    gemm16<0><<<dim3(D / 128, BSR / 128, 1), 256, GEMM_SMEM>>>(
        Oh, Ol, Wo, nullptr, nullptr, out, nullptr, nullptr, nullptr, fc, fs);
}

// round 15
// speedup vs baseline: 1.8506x; 1.8506x over previous
#include <cuda_runtime.h>
#include <cuda_bf16.h>
#include <cuda_fp16.h>
#include <cstdint>

#define D   4096
#define BSR 4096
#define SEQ 1024
#define NH  32
#define HD  128
#define LR  16
#define SCALE 0.08838834764831845f

// ------------------------- device scratch ---------------------------------
__device__ __half g_xh[(size_t)BSR * D];
__device__ __half g_Wq[(size_t)D * D], g_Wk[(size_t)D * D];
__device__ __half g_Wv[(size_t)D * D], g_Wo[(size_t)D * D];
__device__ __half g_Q[(size_t)BSR * D], g_K[(size_t)BSR * D], g_V[(size_t)BSR * D];
__device__ __half g_Oh[(size_t)BSR * D], g_Ol[(size_t)BSR * D];

// ------------------------- PTX helpers (base-target only) ------------------
__device__ __forceinline__ uint32_t smem_to_u32(const void* p) {
    uint32_t a;
    asm("{ .reg .u64 t; cvta.to.shared.u64 t, %1; cvt.u32.u64 %0, t; }"
        : "=r"(a) : "l"(p));
    return a;
}
#define CP16(dst, src) \
    asm volatile("cp.async.cg.shared.global [%0], [%1], 16;" \
                 :: "r"(dst), "l"(src))
#define CP_COMMIT() asm volatile("cp.async.commit_group;" ::: "memory")
#define CP_WAIT1()  asm volatile("cp.async.wait_group 1;" ::: "memory")
#define CP_WAIT0()  asm volatile("cp.async.wait_group 0;" ::: "memory")

#define LDSM4(r0, r1, r2, r3, addr) \
    asm volatile("ldmatrix.sync.aligned.m8n8.x4.shared.b16 {%0,%1,%2,%3}, [%4];" \
                 : "=r"(r0), "=r"(r1), "=r"(r2), "=r"(r3) : "r"(addr))
#define LDSM4T(r0, r1, r2, r3, addr) \
    asm volatile("ldmatrix.sync.aligned.m8n8.x4.trans.shared.b16 {%0,%1,%2,%3}, [%4];" \
                 : "=r"(r0), "=r"(r1), "=r"(r2), "=r"(r3) : "r"(addr))
#define LDSM2(r0, r1, addr) \
    asm volatile("ldmatrix.sync.aligned.m8n8.x2.shared.b16 {%0,%1}, [%2];" \
                 : "=r"(r0), "=r"(r1) : "r"(addr))
#define MMAF16(c, a0, a1, a2, a3, b0, b1) \
    asm volatile("mma.sync.aligned.m16n8k16.row.col.f32.f16.f16.f32 " \
                 "{%0,%1,%2,%3}, {%4,%5,%6,%7}, {%8,%9}, {%0,%1,%2,%3};" \
                 : "+f"((c)[0]), "+f"((c)[1]), "+f"((c)[2]), "+f"((c)[3]) \
                 : "r"(a0), "r"(a1), "r"(a2), "r"(a3), "r"(b0), "r"(b1))

// ------------------------- prep kernels ------------------------------------
// Tiled LoRA merge: block = (k-tile 256, n-tile 512, sel). a-slice in smem.
__global__ void prep_merge(const float* __restrict__ wq_w,
                           const float* __restrict__ wq_a,
                           const float* __restrict__ wq_b,
                           const float* __restrict__ wv_w,
                           const float* __restrict__ wv_a,
                           const float* __restrict__ wv_b,
                           __half* __restrict__ Wq,
                           __half* __restrict__ Wv) {
    const int sel = blockIdx.z;
    const float* w = sel ? wv_w : wq_w;
    const float* a = sel ? wv_a : wq_a;
    const float* b = sel ? wv_b : wq_b;
    __half* o      = sel ? Wv   : Wq;
    const int k0 = blockIdx.x * 256;
    const int n0 = blockIdx.y * 512;
    const int tid = threadIdx.x;

    __shared__ float as[LR][256];
    for (int i = tid; i < LR * 256; i += 256)
        as[i >> 8][i & 255] = a[(i >> 8) * D + k0 + (i & 255)];
    __syncthreads();

    const int k = k0 + tid;
    for (int n = n0; n < n0 + 512; n++) {
        float acc = w[(size_t)n * D + k];
        const float4 b0 = *(const float4*)&b[n * LR];
        const float4 b1 = *(const float4*)&b[n * LR + 4];
        const float4 b2 = *(const float4*)&b[n * LR + 8];
        const float4 b3 = *(const float4*)&b[n * LR + 12];
        acc += 2.0f * (b0.x * as[0][tid]  + b0.y * as[1][tid] +
                       b0.z * as[2][tid]  + b0.w * as[3][tid] +
                       b1.x * as[4][tid]  + b1.y * as[5][tid] +
                       b1.z * as[6][tid]  + b1.w * as[7][tid] +
                       b2.x * as[8][tid]  + b2.y * as[9][tid] +
                       b2.z * as[10][tid] + b2.w * as[11][tid] +
                       b3.x * as[12][tid] + b3.y * as[13][tid] +
                       b3.z * as[14][tid] + b3.w * as[15][tid]);
        o[(size_t)n * D + k] = __float2half_rn(acc);
    }
}

// sel 0: wk -> fp16; sel 1: wo -> fp16; sel 2: x -> fp16 (no split needed).
__global__ void prep_split(const float* __restrict__ wk_w,
                           const float* __restrict__ wo_w,
                           const float* __restrict__ x,
                           __half* __restrict__ Wk,
                           __half* __restrict__ Wo,
                           __half* __restrict__ xh) {
    const int sel = blockIdx.x >> 13;
    const size_t i = (((size_t)(blockIdx.x & 8191) << 8) + threadIdx.x) * 8;
    const float* src = sel == 0 ? wk_w : (sel == 1 ? wo_w : x);
    __half* dst = sel == 0 ? Wk : (sel == 1 ? Wo : xh);
    float v[8];
    *(float4*)&v[0] = *(const float4*)(src + i);
    *(float4*)&v[4] = *(const float4*)(src + i + 4);
    __half h[8];
#pragma unroll
    for (int j = 0; j < 8; j++) h[j] = __float2half_rn(v[j]);
    *(float4*)(dst + i) = *(float4*)h;
}

// ------------- fp16 GEMM (NT), 2 CTAs/SM -----------------------------------
// MODE 0: O projection, 2-term (Oh*Wo + Ol*Wo), 2 stages, fp32 out.
// MODE 1: fused QKV, 1-term (xh*W), 3 stages; blockIdx.z: 0=Q(RoPE+scale),
//         1=K(RoPE), 2=V; fp16 out.
#define GTILE   16384
#define GEMM_SMEM 98304   // MODE0: 2 stages x 48KB; MODE1: 3 stages x 32KB
#define NCHUNK  64        // D / BK

template <int MODE>
__global__ void __launch_bounds__(256, 2) gemm16(
    const __half* __restrict__ Ah, const __half* __restrict__ Al,
    const __half* __restrict__ B0, const __half* __restrict__ B1,
    const __half* __restrict__ B2,
    float* __restrict__ C,
    __half* __restrict__ O0, __half* __restrict__ O1, __half* __restrict__ O2,
    const float* __restrict__ fc, const float* __restrict__ fs) {
    constexpr int TERMS = (MODE == 0) ? 2 : 1;
    constexpr int NST   = (MODE == 0) ? 2 : 3;
    constexpr uint32_t STAGE = (TERMS + 1) * GTILE;

    extern __shared__ char smch[];
    const uint32_t smb = smem_to_u32(smch);
    const int tid = threadIdx.x, lane = tid & 31, wid = tid >> 5;
    const int warp_m = wid & 1;
    const int warp_n = wid >> 1;
    const int bm = blockIdx.y * 128, bn = blockIdx.x * 128;
    const int z = blockIdx.z;
    const __half* B = (MODE == 0) ? B0 : (z == 0 ? B0 : (z == 1 ? B1 : B2));

    float acc[4][4][4];
#pragma unroll
    for (int i = 0; i < 4; i++)
#pragma unroll
        for (int j = 0; j < 4; j++)
#pragma unroll
            for (int k = 0; k < 4; k++) acc[i][j][k] = 0.0f;

    const int r0 = tid >> 3, c0 = tid & 7;
    const uint32_t dst0 = r0 * 128 + (uint32_t)((c0 ^ (r0 & 7)) * 16);
    const __half* gAh = Ah + ((size_t)(bm + r0) << 12) + c0 * 8;
    const __half* gAl = (TERMS == 2) ? Al + ((size_t)(bm + r0) << 12) + c0 * 8 : nullptr;
    const __half* gB  = B  + ((size_t)(bn + r0) << 12) + c0 * 8;

#define ISSUE(ck, st) do {                                                     \
        const uint32_t sb_ = smb + (st) * STAGE + dst0;                        \
        const size_t go_ = (size_t)(ck) * 64;                                  \
        _Pragma("unroll")                                                      \
        for (int j = 0; j < 4; j++) {                                          \
            const uint32_t d_ = sb_ + j * 32 * 128;                            \
            const size_t s_ = go_ + ((size_t)j << 17);                         \
            CP16(d_, (const char*)(gAh + s_));                                 \
            if (TERMS == 2) CP16(d_ + GTILE, (const char*)(gAl + s_));         \
            CP16(d_ + TERMS * GTILE, (const char*)(gB + s_));                  \
        }                                                                      \
        CP_COMMIT();                                                           \
    } while (0)

    ISSUE(0, 0);
    ISSUE(1, 1);

    const int arow = warp_m * 64 + (lane & 15);
    const int akh  = lane >> 4;
    const int brow = warp_n * 32 + (lane & 7);
    const int bkh  = (lane >> 3) & 1;

    for (int ck = 0; ck < NCHUNK; ck++) {
        const int st = (NST == 2) ? (ck & 1) : (ck % 3);
        if (ck + 2 >= NCHUNK) { CP_WAIT0(); } else { CP_WAIT1(); }
        __syncthreads();
        if (NST == 3 && ck + 2 < NCHUNK) ISSUE(ck + 2, (ck + 2) % 3);

        const uint32_t sAh = smb + st * STAGE;
        const uint32_t sAl = sAh + GTILE;
        const uint32_t sB  = sAh + TERMS * GTILE;

#pragma unroll
        for (int ks = 0; ks < 4; ks++) {
            uint32_t bb[4][2];
#pragma unroll
            for (int nt = 0; nt < 4; nt++) {
                const int r = brow + nt * 8;
                const uint32_t adr = r * 128 + (((ks * 2 + bkh) ^ (r & 7)) * 16);
                LDSM2(bb[nt][0], bb[nt][1], sB + adr);
            }
#pragma unroll
            for (int mt = 0; mt < 4; mt++) {
                const int r = arow + mt * 16;
                const uint32_t adr = r * 128 + (((ks * 2 + akh) ^ (r & 7)) * 16);
                uint32_t a0, a1, a2, a3;
                LDSM4(a0, a1, a2, a3, sAh + adr);
#pragma unroll
                for (int nt = 0; nt < 4; nt++)
                    MMAF16(acc[mt][nt], a0, a1, a2, a3, bb[nt][0], bb[nt][1]);
                if (TERMS == 2) {
                    LDSM4(a0, a1, a2, a3, sAl + adr);
#pragma unroll
                    for (int nt = 0; nt < 4; nt++)
                        MMAF16(acc[mt][nt], a0, a1, a2, a3, bb[nt][0], bb[nt][1]);
                }
            }
        }
        if (NST == 2) {
            __syncthreads();
            if (ck + 2 < NCHUNK) ISSUE(ck + 2, ck & 1);
        }
    }

    // epilogue
    __half* outp = (MODE == 1) ? (z == 0 ? O0 : (z == 1 ? O1 : O2)) : (__half*)0;
    const bool doRope  = (MODE == 1) && (z < 2);
    const bool doScale = (MODE == 1) && (z == 0);
#pragma unroll
    for (int mt = 0; mt < 4; mt++) {
        const int row = bm + warp_m * 64 + mt * 16 + (lane >> 2);
#pragma unroll
        for (int nt = 0; nt < 4; nt++) {
            const int col = bn + warp_n * 32 + nt * 8 + (lane & 3) * 2;
            float v0 = acc[mt][nt][0], v1 = acc[mt][nt][1];
            float v2 = acc[mt][nt][2], v3 = acc[mt][nt][3];
            if (doRope) {
                const int i = (col & (HD - 1)) >> 1;
                const int s1 = row & (SEQ - 1);
                const int s2 = (row + 8) & (SEQ - 1);
                const float c1 = __ldg(&fc[s1 * 64 + i]), n1 = __ldg(&fs[s1 * 64 + i]);
                const float c2 = __ldg(&fc[s2 * 64 + i]), n2 = __ldg(&fs[s2 * 64 + i]);
                float t;
                t  = v0 * c1 - v1 * n1; v1 = v0 * n1 + v1 * c1; v0 = t;
                t  = v2 * c2 - v3 * n2; v3 = v2 * n2 + v3 * c2; v2 = t;
            }
            if (doScale) { v0 *= SCALE; v1 *= SCALE; v2 *= SCALE; v3 *= SCALE; }
            if (MODE == 0) {
                *(float2*)&C[(size_t)row * D + col]       = make_float2(v0, v1);
                *(float2*)&C[(size_t)(row + 8) * D + col] = make_float2(v2, v3);
            } else {
                __half2 p; p.x = __float2half_rn(v0); p.y = __float2half_rn(v1);
                *(__half2*)&outp[(size_t)row * D + col] = p;
                __half2 q; q.x = __float2half_rn(v2); q.y = __float2half_rn(v3);
                *(__half2*)&outp[(size_t)(row + 8) * D + col] = q;
            }
        }
    }
}

// ---------------- MMA flash attention (fp16 1-term, causal) ----------------
// R13-proven: BM=128, 256 threads, grid (8, NH, B).
#define AT_Q    0
#define AT_ST   32768
#define AT_STSZ 32768   // K 16KB | V 16KB
#define ATTN_SMEM (AT_ST + 2 * AT_STSZ)

__global__ void __launch_bounds__(256, 1) attn_mma() {
    extern __shared__ char smc[];
    const uint32_t smb = smem_to_u32(smc);
    const int b = blockIdx.z, h = blockIdx.y, qt = blockIdx.x;
    const int q0 = qt * 128;
    const int tid = threadIdx.x, lane = tid & 31, wid = tid >> 5;

    const size_t qoff = ((size_t)(b * SEQ + q0) << 12) + (size_t)h * HD;
    const size_t koff = ((size_t)(b * SEQ) << 12) + (size_t)h * HD;

#pragma unroll
    for (int j = 0; j < 8; j++) {
        int q = tid + 256 * j;
        int r = q >> 4, dt = q & 15;
        int srow = 2 * r + (dt >> 3);
        uint32_t adr = srow * 128 + (uint32_t)((((dt & 7)) ^ (srow & 7)) * 16);
        CP16(smb + AT_Q + adr, (const char*)(g_Q + qoff + ((size_t)r << 12) + dt * 8));
    }

#define ISSUE_KV(kt, st) do {                                                  \
        const size_t kb_ = koff + ((size_t)((kt) * 64) << 12);                 \
        const uint32_t sb_ = smb + AT_ST + (st) * AT_STSZ;                     \
        _Pragma("unroll")                                                      \
        for (int j = 0; j < 4; j++) {                                          \
            int q_ = tid + 256 * j;                                            \
            int r_ = q_ >> 4, dt_ = q_ & 15;                                   \
            int sr_ = 2 * r_ + (dt_ >> 3);                                     \
            uint32_t ad_ = sr_ * 128 + (uint32_t)(((dt_ & 7) ^ (sr_ & 7)) * 16); \
            const size_t g_ = kb_ + ((size_t)r_ << 12) + dt_ * 8;              \
            CP16(sb_ + ad_,         (const char*)(g_K + g_));                  \
            CP16(sb_ + 16384 + ad_, (const char*)(g_V + g_));                  \
        }                                                                      \
        CP_COMMIT();                                                           \
    } while (0)

    ISSUE_KV(0, 0);

    float o[16][4];
#pragma unroll
    for (int i = 0; i < 16; i++)
#pragma unroll
        for (int j = 0; j < 4; j++) o[i][j] = 0.0f;
    float m[2] = {-1e30f, -1e30f}, lsum[2] = {0.0f, 0.0f};

    const int ktiles = 2 * qt + 2;
    const int ar = wid * 16 + (lane & 15);
    const int akh = lane >> 4;

    for (int kt = 0; kt < ktiles; kt++) {
        const int st = kt & 1;
        if (kt + 1 < ktiles) { ISSUE_KV(kt + 1, st ^ 1); CP_WAIT1(); }
        else                 { CP_WAIT0(); }
        __syncthreads();

        const uint32_t sQ = smb + AT_Q;
        const uint32_t sK = smb + AT_ST + st * AT_STSZ;
        const uint32_t sV = sK + 16384;

        float sc[8][4];
#pragma unroll
        for (int t = 0; t < 8; t++)
#pragma unroll
            for (int j = 0; j < 4; j++) sc[t][j] = 0.0f;

#pragma unroll
        for (int ks = 0; ks < 8; ks++) {
            const int qs = 2 * ar + (ks >> 2);
            const uint32_t aadr = qs * 128 +
                (uint32_t)(((((ks & 3) * 2 + akh)) ^ (qs & 7)) * 16);
            uint32_t qf[4];
            LDSM4(qf[0], qf[1], qf[2], qf[3], sQ + aadr);
#pragma unroll
            for (int ntp = 0; ntp < 4; ntp++) {
                const int kr = ((lane >> 4) ? (2 * ntp + 1) : (2 * ntp)) * 8 + (lane & 7);
                const int kkh = (lane >> 3) & 1;
                const int ksr = 2 * kr + (ks >> 2);
                const uint32_t kadr = ksr * 128 +
                    (uint32_t)(((((ks & 3) * 2 + kkh)) ^ (ksr & 7)) * 16);
                uint32_t kf[4];
                LDSM4(kf[0], kf[1], kf[2], kf[3], sK + kadr);
                MMAF16(sc[2*ntp],   qf[0], qf[1], qf[2], qf[3], kf[0], kf[1]);
                MMAF16(sc[2*ntp+1], qf[0], qf[1], qf[2], qf[3], kf[2], kf[3]);
            }
        }

        const int k0 = kt * 64;
        if (k0 + 63 > q0) {
            const int rb = q0 + wid * 16 + (lane >> 2);
#pragma unroll
            for (int t = 0; t < 8; t++) {
                const int cb = k0 + t * 8 + (lane & 3) * 2;
                if (cb     > rb)     sc[t][0] = -1e30f;
                if (cb + 1 > rb)     sc[t][1] = -1e30f;
                if (cb     > rb + 8) sc[t][2] = -1e30f;
                if (cb + 1 > rb + 8) sc[t][3] = -1e30f;
            }
        }

#pragma unroll
        for (int rh = 0; rh < 2; rh++) {
            float mx = -1e30f;
#pragma unroll
            for (int t = 0; t < 8; t++)
                mx = fmaxf(mx, fmaxf(sc[t][2*rh], sc[t][2*rh+1]));
            mx = fmaxf(mx, __shfl_xor_sync(0xffffffffu, mx, 1));
            mx = fmaxf(mx, __shfl_xor_sync(0xffffffffu, mx, 2));
            const float mnew = fmaxf(m[rh], mx);
            const float alpha = __expf(m[rh] - mnew);
            float s = 0.0f;
#pragma unroll
            for (int t = 0; t < 8; t++) {
                float p0 = __expf(sc[t][2*rh]   - mnew);
                float p1 = __expf(sc[t][2*rh+1] - mnew);
                sc[t][2*rh] = p0; sc[t][2*rh+1] = p1;
                s += p0 + p1;
            }
            s += __shfl_xor_sync(0xffffffffu, s, 1);
            s += __shfl_xor_sync(0xffffffffu, s, 2);
            lsum[rh] = lsum[rh] * alpha + s;
            m[rh] = mnew;
#pragma unroll
            for (int dt = 0; dt < 16; dt++) {
                o[dt][2*rh]   *= alpha;
                o[dt][2*rh+1] *= alpha;
            }
        }

#pragma unroll
        for (int kj = 0; kj < 4; kj++) {
            uint32_t ph[4];
#pragma unroll
            for (int u = 0; u < 4; u++) {
                const float* sp = sc[2 * kj + (u >> 1)];
                __half2 hp;
                hp.x = __float2half_rn(sp[(u & 1) * 2]);
                hp.y = __float2half_rn(sp[(u & 1) * 2 + 1]);
                ph[u] = *(uint32_t*)&hp;
            }
            const int jr = kj * 16 + (lane & 7) + (((lane >> 3) & 1) << 3);
#pragma unroll
            for (int npp = 0; npp < 4; npp++) {
                const int np0 = 2 * npp, np1 = 2 * npp + 1;
                uint32_t vA[4], vB[4];
                {
                    const int dtc = 2 * np0 + (lane >> 4);
                    const int vsr = 2 * jr + (dtc >> 3);
                    const uint32_t vadr = vsr * 128 +
                        (uint32_t)((((dtc & 7)) ^ (vsr & 7)) * 16);
                    LDSM4T(vA[0], vA[1], vA[2], vA[3], sV + vadr);
                }
                {
                    const int dtc = 2 * np1 + (lane >> 4);
                    const int vsr = 2 * jr + (dtc >> 3);
                    const uint32_t vadr = vsr * 128 +
                        (uint32_t)((((dtc & 7)) ^ (vsr & 7)) * 16);
                    LDSM4T(vB[0], vB[1], vB[2], vB[3], sV + vadr);
                }
                MMAF16(o[2*np0],   ph[0], ph[1], ph[2], ph[3], vA[0], vA[1]);
                MMAF16(o[2*np0+1], ph[0], ph[1], ph[2], ph[3], vA[2], vA[3]);
                MMAF16(o[2*np1],   ph[0], ph[1], ph[2], ph[3], vB[0], vB[1]);
                MMAF16(o[2*np1+1], ph[0], ph[1], ph[2], ph[3], vB[2], vB[3]);
            }
        }
        __syncthreads();
    }

    // ---- epilogue: normalize + fp16 hi/lo split (feeds 2-term O-GEMM) ----
#pragma unroll
    for (int rh = 0; rh < 2; rh++) {
        const float inv = 1.0f / lsum[rh];
        const int row = q0 + wid * 16 + (lane >> 2) + rh * 8;
        const size_t ro = ((size_t)(b * SEQ + row) << 12) + (size_t)h * HD
                          + (lane & 3) * 2;
#pragma unroll
        for (int dt = 0; dt < 16; dt++) {
            const float v0 = o[dt][2*rh] * inv, v1 = o[dt][2*rh+1] * inv;
            __half h0 = __float2half_rn(v0), h1 = __float2half_rn(v1);
            __half2 hp; hp.x = h0; hp.y = h1;
            *(__half2*)&g_Oh[ro + dt * 8] = hp;
            __half2 lp;
            lp.x = __float2half_rn(v0 - __half2float(h0));
            lp.y = __float2half_rn(v1 - __half2float(h1));
            *(__half2*)&g_Ol[ro + dt * 8] = lp;
        }
    }
}

// ---------------- launcher -------------------------------------------------
extern "C" void kernel_launch(void* const* d_in, const int* in_sizes, int n_in,
                              void* d_out, int out_size) {
    const float* x    = (const float*)d_in[0];
    const float* wq_w = (const float*)d_in[1];
    const float* wq_a = (const float*)d_in[2];
    const float* wq_b = (const float*)d_in[3];
    const float* wk_w = (const float*)d_in[4];
    const float* wv_w = (const float*)d_in[5];
    const float* wv_a = (const float*)d_in[6];
    const float* wv_b = (const float*)d_in[7];
    const float* wo_w = (const float*)d_in[8];
    const float* fc   = (const float*)d_in[9];
    const float* fs   = (const float*)d_in[10];
    float* out = (float*)d_out;

    __half *xh, *Wq, *Wk, *Wv, *Wo, *Q, *K, *V, *Oh, *Ol;
    cudaGetSymbolAddress((void**)&xh, g_xh);
    cudaGetSymbolAddress((void**)&Wq, g_Wq); cudaGetSymbolAddress((void**)&Wk, g_Wk);
    cudaGetSymbolAddress((void**)&Wv, g_Wv); cudaGetSymbolAddress((void**)&Wo, g_Wo);
    cudaGetSymbolAddress((void**)&Q, g_Q);   cudaGetSymbolAddress((void**)&K, g_K);
    cudaGetSymbolAddress((void**)&V, g_V);
    cudaGetSymbolAddress((void**)&Oh, g_Oh); cudaGetSymbolAddress((void**)&Ol, g_Ol);

    cudaFuncSetAttribute(gemm16<0>, cudaFuncAttributeMaxDynamicSharedMemorySize, GEMM_SMEM);
    cudaFuncSetAttribute(gemm16<1>, cudaFuncAttributeMaxDynamicSharedMemorySize, GEMM_SMEM);
    cudaFuncSetAttribute(attn_mma, cudaFuncAttributeMaxDynamicSharedMemorySize, ATTN_SMEM);

    // 1) prep: tiled LoRA merge (Wq, Wv); fp16 casts (Wk, Wo, x)
    prep_merge<<<dim3(16, 8, 2), 256>>>(wq_w, wq_a, wq_b, wv_w, wv_a, wv_b, Wq, Wv);
    prep_split<<<3 * 8192, 256>>>(wk_w, wo_w, x, Wk, Wo, xh);

    // 2) fused QKV projection (fp16 1-term, 3-stage, 2 CTAs/SM)
    gemm16<1><<<dim3(D / 128, BSR / 128, 3), 256, GEMM_SMEM>>>(
        xh, nullptr, Wq, Wk, Wv, nullptr, Q, K, V, fc, fs);

    // 3) fp16 1-term MMA flash attention (R13 config) -> g_Oh/g_Ol
    attn_mma<<<dim3(SEQ / 128, NH, 4), 256, ATTN_SMEM>>>();

    // 4) output projection (fp16 2-term exact-O, fp32 out)
    gemm16<0><<<dim3(D / 128, BSR / 128, 1), 256, GEMM_SMEM>>>(
        Oh, Ol, Wo, nullptr, nullptr, out, nullptr, nullptr, nullptr, fc, fs);
}

// round 16
// speedup vs baseline: 1.8781x; 1.0148x over previous
#include <cuda_runtime.h>
#include <cuda_bf16.h>
#include <cuda_fp16.h>
#include <cstdint>

#define D   4096
#define BSR 4096
#define SEQ 1024
#define NH  32
#define HD  128
#define LR  16
#define SCALE 0.08838834764831845f

// ------------------------- device scratch ---------------------------------
__device__ __half g_xh[(size_t)BSR * D];
__device__ __half g_Wq[(size_t)D * D], g_Wk[(size_t)D * D];
__device__ __half g_Wv[(size_t)D * D], g_Wo[(size_t)D * D];
__device__ __half g_Q[(size_t)BSR * D], g_K[(size_t)BSR * D], g_V[(size_t)BSR * D];
__device__ __half g_Oh[(size_t)BSR * D], g_Ol[(size_t)BSR * D];

// ------------------------- PTX helpers (base-target only) ------------------
__device__ __forceinline__ uint32_t smem_to_u32(const void* p) {
    uint32_t a;
    asm("{ .reg .u64 t; cvta.to.shared.u64 t, %1; cvt.u32.u64 %0, t; }"
        : "=r"(a) : "l"(p));
    return a;
}
#define CP16(dst, src) \
    asm volatile("cp.async.cg.shared.global [%0], [%1], 16;" \
                 :: "r"(dst), "l"(src))
#define CP_COMMIT() asm volatile("cp.async.commit_group;" ::: "memory")
#define CP_WAIT1()  asm volatile("cp.async.wait_group 1;" ::: "memory")
#define CP_WAIT0()  asm volatile("cp.async.wait_group 0;" ::: "memory")

#define LDSM4(r0, r1, r2, r3, addr) \
    asm volatile("ldmatrix.sync.aligned.m8n8.x4.shared.b16 {%0,%1,%2,%3}, [%4];" \
                 : "=r"(r0), "=r"(r1), "=r"(r2), "=r"(r3) : "r"(addr))
#define LDSM4T(r0, r1, r2, r3, addr) \
    asm volatile("ldmatrix.sync.aligned.m8n8.x4.trans.shared.b16 {%0,%1,%2,%3}, [%4];" \
                 : "=r"(r0), "=r"(r1), "=r"(r2), "=r"(r3) : "r"(addr))
#define LDSM2(r0, r1, addr) \
    asm volatile("ldmatrix.sync.aligned.m8n8.x2.shared.b16 {%0,%1}, [%2];" \
                 : "=r"(r0), "=r"(r1) : "r"(addr))
#define MMAF16(c, a0, a1, a2, a3, b0, b1) \
    asm volatile("mma.sync.aligned.m16n8k16.row.col.f32.f16.f16.f32 " \
                 "{%0,%1,%2,%3}, {%4,%5,%6,%7}, {%8,%9}, {%0,%1,%2,%3};" \
                 : "+f"((c)[0]), "+f"((c)[1]), "+f"((c)[2]), "+f"((c)[3]) \
                 : "r"(a0), "r"(a1), "r"(a2), "r"(a3), "r"(b0), "r"(b1))

// ------------------------- prep kernels ------------------------------------
__global__ void prep_merge(const float* __restrict__ wq_w,
                           const float* __restrict__ wq_a,
                           const float* __restrict__ wq_b,
                           const float* __restrict__ wv_w,
                           const float* __restrict__ wv_a,
                           const float* __restrict__ wv_b,
                           __half* __restrict__ Wq,
                           __half* __restrict__ Wv) {
    const int sel = blockIdx.z;
    const float* w = sel ? wv_w : wq_w;
    const float* a = sel ? wv_a : wq_a;
    const float* b = sel ? wv_b : wq_b;
    __half* o      = sel ? Wv   : Wq;
    const int k0 = blockIdx.x * 256;
    const int n0 = blockIdx.y * 512;
    const int tid = threadIdx.x;

    __shared__ float as[LR][256];
    for (int i = tid; i < LR * 256; i += 256)
        as[i >> 8][i & 255] = a[(i >> 8) * D + k0 + (i & 255)];
    __syncthreads();

    const int k = k0 + tid;
    for (int n = n0; n < n0 + 512; n++) {
        float acc = w[(size_t)n * D + k];
        const float4 b0 = *(const float4*)&b[n * LR];
        const float4 b1 = *(const float4*)&b[n * LR + 4];
        const float4 b2 = *(const float4*)&b[n * LR + 8];
        const float4 b3 = *(const float4*)&b[n * LR + 12];
        acc += 2.0f * (b0.x * as[0][tid]  + b0.y * as[1][tid] +
                       b0.z * as[2][tid]  + b0.w * as[3][tid] +
                       b1.x * as[4][tid]  + b1.y * as[5][tid] +
                       b1.z * as[6][tid]  + b1.w * as[7][tid] +
                       b2.x * as[8][tid]  + b2.y * as[9][tid] +
                       b2.z * as[10][tid] + b2.w * as[11][tid] +
                       b3.x * as[12][tid] + b3.y * as[13][tid] +
                       b3.z * as[14][tid] + b3.w * as[15][tid]);
        o[(size_t)n * D + k] = __float2half_rn(acc);
    }
}

__global__ void prep_split(const float* __restrict__ wk_w,
                           const float* __restrict__ wo_w,
                           const float* __restrict__ x,
                           __half* __restrict__ Wk,
                           __half* __restrict__ Wo,
                           __half* __restrict__ xh) {
    const int sel = blockIdx.x >> 13;
    const size_t i = (((size_t)(blockIdx.x & 8191) << 8) + threadIdx.x) * 8;
    const float* src = sel == 0 ? wk_w : (sel == 1 ? wo_w : x);
    __half* dst = sel == 0 ? Wk : (sel == 1 ? Wo : xh);
    float v[8];
    *(float4*)&v[0] = *(const float4*)(src + i);
    *(float4*)&v[4] = *(const float4*)(src + i + 4);
    __half h[8];
#pragma unroll
    for (int j = 0; j < 8; j++) h[j] = __float2half_rn(v[j]);
    *(float4*)(dst + i) = *(float4*)h;
}

// ------------- fp16 GEMM (NT), 2 CTAs/SM -----------------------------------
// MODE 0: O projection, 2-term (Oh*Wo + Ol*Wo), 2 stages, fp32 out.
// MODE 1: fused QKV, 1-term (xh*W), 3 stages; blockIdx.z: 0=Q(RoPE+scale),
//         1=K(RoPE), 2=V; fp16 out.
#define GTILE   16384
#define GEMM_SMEM 98304
#define NCHUNK  64

template <int MODE>
__global__ void __launch_bounds__(256, 2) gemm16(
    const __half* __restrict__ Ah, const __half* __restrict__ Al,
    const __half* __restrict__ B0, const __half* __restrict__ B1,
    const __half* __restrict__ B2,
    float* __restrict__ C,
    __half* __restrict__ O0, __half* __restrict__ O1, __half* __restrict__ O2,
    const float* __restrict__ fc, const float* __restrict__ fs) {
    constexpr int TERMS = (MODE == 0) ? 2 : 1;
    constexpr int NST   = (MODE == 0) ? 2 : 3;
    constexpr uint32_t STAGE = (TERMS + 1) * GTILE;

    extern __shared__ char smch[];
    const uint32_t smb = smem_to_u32(smch);
    const int tid = threadIdx.x, lane = tid & 31, wid = tid >> 5;
    const int warp_m = wid & 1;
    const int warp_n = wid >> 1;
    const int bm = blockIdx.y * 128, bn = blockIdx.x * 128;
    const int z = blockIdx.z;
    const __half* B = (MODE == 0) ? B0 : (z == 0 ? B0 : (z == 1 ? B1 : B2));

    float acc[4][4][4];
#pragma unroll
    for (int i = 0; i < 4; i++)
#pragma unroll
        for (int j = 0; j < 4; j++)
#pragma unroll
            for (int k = 0; k < 4; k++) acc[i][j][k] = 0.0f;

    const int r0 = tid >> 3, c0 = tid & 7;
    const uint32_t dst0 = r0 * 128 + (uint32_t)((c0 ^ (r0 & 7)) * 16);
    const __half* gAh = Ah + ((size_t)(bm + r0) << 12) + c0 * 8;
    const __half* gAl = (TERMS == 2) ? Al + ((size_t)(bm + r0) << 12) + c0 * 8 : nullptr;
    const __half* gB  = B  + ((size_t)(bn + r0) << 12) + c0 * 8;

#define ISSUE(ck, st) do {                                                     \
        const uint32_t sb_ = smb + (st) * STAGE + dst0;                        \
        const size_t go_ = (size_t)(ck) * 64;                                  \
        _Pragma("unroll")                                                      \
        for (int j = 0; j < 4; j++) {                                          \
            const uint32_t d_ = sb_ + j * 32 * 128;                            \
            const size_t s_ = go_ + ((size_t)j << 17);                         \
            CP16(d_, (const char*)(gAh + s_));                                 \
            if (TERMS == 2) CP16(d_ + GTILE, (const char*)(gAl + s_));         \
            CP16(d_ + TERMS * GTILE, (const char*)(gB + s_));                  \
        }                                                                      \
        CP_COMMIT();                                                           \
    } while (0)

    ISSUE(0, 0);
    ISSUE(1, 1);

    const int arow = warp_m * 64 + (lane & 15);
    const int akh  = lane >> 4;
    const int brow = warp_n * 32 + (lane & 7);
    const int bkh  = (lane >> 3) & 1;

    for (int ck = 0; ck < NCHUNK; ck++) {
        const int st = (NST == 2) ? (ck & 1) : (ck % 3);
        if (ck + 2 >= NCHUNK) { CP_WAIT0(); } else { CP_WAIT1(); }
        __syncthreads();
        if (NST == 3 && ck + 2 < NCHUNK) ISSUE(ck + 2, (ck + 2) % 3);

        const uint32_t sAh = smb + st * STAGE;
        const uint32_t sAl = sAh + GTILE;
        const uint32_t sB  = sAh + TERMS * GTILE;

#pragma unroll
        for (int ks = 0; ks < 4; ks++) {
            uint32_t bb[4][2];
#pragma unroll
            for (int nt = 0; nt < 4; nt++) {
                const int r = brow + nt * 8;
                const uint32_t adr = r * 128 + (((ks * 2 + bkh) ^ (r & 7)) * 16);
                LDSM2(bb[nt][0], bb[nt][1], sB + adr);
            }
#pragma unroll
            for (int mt = 0; mt < 4; mt++) {
                const int r = arow + mt * 16;
                const uint32_t adr = r * 128 + (((ks * 2 + akh) ^ (r & 7)) * 16);
                uint32_t a0, a1, a2, a3;
                LDSM4(a0, a1, a2, a3, sAh + adr);
#pragma unroll
                for (int nt = 0; nt < 4; nt++)
                    MMAF16(acc[mt][nt], a0, a1, a2, a3, bb[nt][0], bb[nt][1]);
                if (TERMS == 2) {
                    LDSM4(a0, a1, a2, a3, sAl + adr);
#pragma unroll
                    for (int nt = 0; nt < 4; nt++)
                        MMAF16(acc[mt][nt], a0, a1, a2, a3, bb[nt][0], bb[nt][1]);
                }
            }
        }
        if (NST == 2) {
            __syncthreads();
            if (ck + 2 < NCHUNK) ISSUE(ck + 2, ck & 1);
        }
    }

    // epilogue
    __half* outp = (MODE == 1) ? (z == 0 ? O0 : (z == 1 ? O1 : O2)) : (__half*)0;
    const bool doRope  = (MODE == 1) && (z < 2);
    const bool doScale = (MODE == 1) && (z == 0);
#pragma unroll
    for (int mt = 0; mt < 4; mt++) {
        const int row = bm + warp_m * 64 + mt * 16 + (lane >> 2);
#pragma unroll
        for (int nt = 0; nt < 4; nt++) {
            const int col = bn + warp_n * 32 + nt * 8 + (lane & 3) * 2;
            float v0 = acc[mt][nt][0], v1 = acc[mt][nt][1];
            float v2 = acc[mt][nt][2], v3 = acc[mt][nt][3];
            if (doRope) {
                const int i = (col & (HD - 1)) >> 1;
                const int s1 = row & (SEQ - 1);
                const int s2 = (row + 8) & (SEQ - 1);
                const float c1 = __ldg(&fc[s1 * 64 + i]), n1 = __ldg(&fs[s1 * 64 + i]);
                const float c2 = __ldg(&fc[s2 * 64 + i]), n2 = __ldg(&fs[s2 * 64 + i]);
                float t;
                t  = v0 * c1 - v1 * n1; v1 = v0 * n1 + v1 * c1; v0 = t;
                t  = v2 * c2 - v3 * n2; v3 = v2 * n2 + v3 * c2; v2 = t;
            }
            if (doScale) { v0 *= SCALE; v1 *= SCALE; v2 *= SCALE; v3 *= SCALE; }
            if (MODE == 0) {
                *(float2*)&C[(size_t)row * D + col]       = make_float2(v0, v1);
                *(float2*)&C[(size_t)(row + 8) * D + col] = make_float2(v2, v3);
            } else {
                __half2 p; p.x = __float2half_rn(v0); p.y = __float2half_rn(v1);
                *(__half2*)&outp[(size_t)row * D + col] = p;
                __half2 q; q.x = __float2half_rn(v2); q.y = __float2half_rn(v3);
                *(__half2*)&outp[(size_t)(row + 8) * D + col] = q;
            }
        }
    }
}

// ---------------- MMA flash attention (fp16 1-term, causal) ----------------
// BM=128, BN=128 (half the softmax passes / barriers / Q reloads of R15).
// 256 threads, 8 warps x 16 q-rows. Grid (8, NH, B), largest-first qt.
// Q 32KB + 2 stages x (K 32KB | V 32KB) = 160KB smem.
#define AT_Q    0
#define AT_ST   32768
#define AT_STSZ 65536   // K 32KB | V 32KB
#define ATTN_SMEM (AT_ST + 2 * AT_STSZ)

__global__ void __launch_bounds__(256, 1) attn_mma() {
    extern __shared__ char smc[];
    const uint32_t smb = smem_to_u32(smc);
    const int b = blockIdx.z, h = blockIdx.y;
    const int qt = (SEQ / 128 - 1) - blockIdx.x;   // largest-first
    const int q0 = qt * 128;
    const int tid = threadIdx.x, lane = tid & 31, wid = tid >> 5;

    const size_t qoff = ((size_t)(b * SEQ + q0) << 12) + (size_t)h * HD;
    const size_t koff = ((size_t)(b * SEQ) << 12) + (size_t)h * HD;

    // Q load: 128 rows x 16 chunks = 2048 chunks, 8/thread
#pragma unroll
    for (int j = 0; j < 8; j++) {
        int q = tid + 256 * j;
        int r = q >> 4, dt = q & 15;
        int srow = 2 * r + (dt >> 3);
        uint32_t adr = srow * 128 + (uint32_t)((((dt & 7)) ^ (srow & 7)) * 16);
        CP16(smb + AT_Q + adr, (const char*)(g_Q + qoff + ((size_t)r << 12) + dt * 8));
    }

    // K/V tile: 128 rows x 16 chunks x 2 tensors = 4096 CP16, 16/thread
#define ISSUE_KV(kt, st) do {                                                  \
        const size_t kb_ = koff + ((size_t)((kt) * 128) << 12);                \
        const uint32_t sb_ = smb + AT_ST + (st) * AT_STSZ;                     \
        _Pragma("unroll")                                                      \
        for (int j = 0; j < 8; j++) {                                          \
            int q_ = tid + 256 * j;                                            \
            int r_ = q_ >> 4, dt_ = q_ & 15;                                   \
            int sr_ = 2 * r_ + (dt_ >> 3);                                     \
            uint32_t ad_ = sr_ * 128 + (uint32_t)(((dt_ & 7) ^ (sr_ & 7)) * 16); \
            const size_t g_ = kb_ + ((size_t)r_ << 12) + dt_ * 8;              \
            CP16(sb_ + ad_,         (const char*)(g_K + g_));                  \
            CP16(sb_ + 32768 + ad_, (const char*)(g_V + g_));                  \
        }                                                                      \
        CP_COMMIT();                                                           \
    } while (0)

    ISSUE_KV(0, 0);

    float o[16][4];
#pragma unroll
    for (int i = 0; i < 16; i++)
#pragma unroll
        for (int j = 0; j < 4; j++) o[i][j] = 0.0f;
    float m[2] = {-1e30f, -1e30f}, lsum[2] = {0.0f, 0.0f};

    const int ktiles = qt + 1;
    const int ar = wid * 16 + (lane & 15);
    const int akh = lane >> 4;

    for (int kt = 0; kt < ktiles; kt++) {
        const int st = kt & 1;
        if (kt + 1 < ktiles) { ISSUE_KV(kt + 1, st ^ 1); CP_WAIT1(); }
        else                 { CP_WAIT0(); }
        __syncthreads();

        const uint32_t sQ = smb + AT_Q;
        const uint32_t sK = smb + AT_ST + st * AT_STSZ;
        const uint32_t sV = sK + 32768;

        // ---- S = Q K^T over 128 k-cols ----
        float sc[16][4];
#pragma unroll
        for (int t = 0; t < 16; t++)
#pragma unroll
            for (int j = 0; j < 4; j++) sc[t][j] = 0.0f;

#pragma unroll
        for (int ks = 0; ks < 8; ks++) {
            const int qs = 2 * ar + (ks >> 2);
            const uint32_t aadr = qs * 128 +
                (uint32_t)(((((ks & 3) * 2 + akh)) ^ (qs & 7)) * 16);
            uint32_t qf[4];
            LDSM4(qf[0], qf[1], qf[2], qf[3], sQ + aadr);
#pragma unroll
            for (int ntp = 0; ntp < 8; ntp++) {
                const int kr = ((lane >> 4) ? (2 * ntp + 1) : (2 * ntp)) * 8 + (lane & 7);
                const int kkh = (lane >> 3) & 1;
                const int ksr = 2 * kr + (ks >> 2);
                const uint32_t kadr = ksr * 128 +
                    (uint32_t)(((((ks & 3) * 2 + kkh)) ^ (ksr & 7)) * 16);
                uint32_t kf[4];
                LDSM4(kf[0], kf[1], kf[2], kf[3], sK + kadr);
                MMAF16(sc[2*ntp],   qf[0], qf[1], qf[2], qf[3], kf[0], kf[1]);
                MMAF16(sc[2*ntp+1], qf[0], qf[1], qf[2], qf[3], kf[2], kf[3]);
            }
        }

        // ---- causal mask (diagonal tile kt == qt) ----
        const int k0 = kt * 128;
        if (kt == qt) {
            const int rb = q0 + wid * 16 + (lane >> 2);
#pragma unroll
            for (int t = 0; t < 16; t++) {
                const int cb = k0 + t * 8 + (lane & 3) * 2;
                if (cb     > rb)     sc[t][0] = -1e30f;
                if (cb + 1 > rb)     sc[t][1] = -1e30f;
                if (cb     > rb + 8) sc[t][2] = -1e30f;
                if (cb + 1 > rb + 8) sc[t][3] = -1e30f;
            }
        }

        // ---- online softmax over 128 cols ----
#pragma unroll
        for (int rh = 0; rh < 2; rh++) {
            float mx = -1e30f;
#pragma unroll
            for (int t = 0; t < 16; t++)
                mx = fmaxf(mx, fmaxf(sc[t][2*rh], sc[t][2*rh+1]));
            mx = fmaxf(mx, __shfl_xor_sync(0xffffffffu, mx, 1));
            mx = fmaxf(mx, __shfl_xor_sync(0xffffffffu, mx, 2));
            const float mnew = fmaxf(m[rh], mx);
            const float alpha = __expf(m[rh] - mnew);
            float s = 0.0f;
#pragma unroll
            for (int t = 0; t < 16; t++) {
                float p0 = __expf(sc[t][2*rh]   - mnew);
                float p1 = __expf(sc[t][2*rh+1] - mnew);
                sc[t][2*rh] = p0; sc[t][2*rh+1] = p1;
                s += p0 + p1;
            }
            s += __shfl_xor_sync(0xffffffffu, s, 1);
            s += __shfl_xor_sync(0xffffffffu, s, 2);
            lsum[rh] = lsum[rh] * alpha + s;
            m[rh] = mnew;
#pragma unroll
            for (int dt = 0; dt < 16; dt++) {
                o[dt][2*rh]   *= alpha;
                o[dt][2*rh+1] *= alpha;
            }
        }

        // ---- O += P V over 128 k-rows ----
#pragma unroll
        for (int kj = 0; kj < 8; kj++) {
            uint32_t ph[4];
#pragma unroll
            for (int u = 0; u < 4; u++) {
                const float* sp = sc[2 * kj + (u >> 1)];
                __half2 hp;
                hp.x = __float2half_rn(sp[(u & 1) * 2]);
                hp.y = __float2half_rn(sp[(u & 1) * 2 + 1]);
                ph[u] = *(uint32_t*)&hp;
            }
            const int jr = kj * 16 + (lane & 7) + (((lane >> 3) & 1) << 3);
#pragma unroll
            for (int npp = 0; npp < 4; npp++) {
                const int np0 = 2 * npp, np1 = 2 * npp + 1;
                uint32_t vA[4], vB[4];
                {
                    const int dtc = 2 * np0 + (lane >> 4);
                    const int vsr = 2 * jr + (dtc >> 3);
                    const uint32_t vadr = vsr * 128 +
                        (uint32_t)((((dtc & 7)) ^ (vsr & 7)) * 16);
                    LDSM4T(vA[0], vA[1], vA[2], vA[3], sV + vadr);
                }
                {
                    const int dtc = 2 * np1 + (lane >> 4);
                    const int vsr = 2 * jr + (dtc >> 3);
                    const uint32_t vadr = vsr * 128 +
                        (uint32_t)((((dtc & 7)) ^ (vsr & 7)) * 16);
                    LDSM4T(vB[0], vB[1], vB[2], vB[3], sV + vadr);
                }
                MMAF16(o[2*np0],   ph[0], ph[1], ph[2], ph[3], vA[0], vA[1]);
                MMAF16(o[2*np0+1], ph[0], ph[1], ph[2], ph[3], vA[2], vA[3]);
                MMAF16(o[2*np1],   ph[0], ph[1], ph[2], ph[3], vB[0], vB[1]);
                MMAF16(o[2*np1+1], ph[0], ph[1], ph[2], ph[3], vB[2], vB[3]);
            }
        }
        __syncthreads();
    }

    // ---- epilogue: normalize + fp16 hi/lo split (feeds 2-term O-GEMM) ----
#pragma unroll
    for (int rh = 0; rh < 2; rh++) {
        const float inv = 1.0f / lsum[rh];
        const int row = q0 + wid * 16 + (lane >> 2) + rh * 8;
        const size_t ro = ((size_t)(b * SEQ + row) << 12) + (size_t)h * HD
                          + (lane & 3) * 2;
#pragma unroll
        for (int dt = 0; dt < 16; dt++) {
            const float v0 = o[dt][2*rh] * inv, v1 = o[dt][2*rh+1] * inv;
            __half h0 = __float2half_rn(v0), h1 = __float2half_rn(v1);
            __half2 hp; hp.x = h0; hp.y = h1;
            *(__half2*)&g_Oh[ro + dt * 8] = hp;
            __half2 lp;
            lp.x = __float2half_rn(v0 - __half2float(h0));
            lp.y = __float2half_rn(v1 - __half2float(h1));
            *(__half2*)&g_Ol[ro + dt * 8] = lp;
        }
    }
}

// ---------------- launcher -------------------------------------------------
extern "C" void kernel_launch(void* const* d_in, const int* in_sizes, int n_in,
                              void* d_out, int out_size) {
    const float* x    = (const float*)d_in[0];
    const float* wq_w = (const float*)d_in[1];
    const float* wq_a = (const float*)d_in[2];
    const float* wq_b = (const float*)d_in[3];
    const float* wk_w = (const float*)d_in[4];
    const float* wv_w = (const float*)d_in[5];
    const float* wv_a = (const float*)d_in[6];
    const float* wv_b = (const float*)d_in[7];
    const float* wo_w = (const float*)d_in[8];
    const float* fc   = (const float*)d_in[9];
    const float* fs   = (const float*)d_in[10];
    float* out = (float*)d_out;

    __half *xh, *Wq, *Wk, *Wv, *Wo, *Q, *K, *V, *Oh, *Ol;
    cudaGetSymbolAddress((void**)&xh, g_xh);
    cudaGetSymbolAddress((void**)&Wq, g_Wq); cudaGetSymbolAddress((void**)&Wk, g_Wk);
    cudaGetSymbolAddress((void**)&Wv, g_Wv); cudaGetSymbolAddress((void**)&Wo, g_Wo);
    cudaGetSymbolAddress((void**)&Q, g_Q);   cudaGetSymbolAddress((void**)&K, g_K);
    cudaGetSymbolAddress((void**)&V, g_V);
    cudaGetSymbolAddress((void**)&Oh, g_Oh); cudaGetSymbolAddress((void**)&Ol, g_Ol);

    cudaFuncSetAttribute(gemm16<0>, cudaFuncAttributeMaxDynamicSharedMemorySize, GEMM_SMEM);
    cudaFuncSetAttribute(gemm16<1>, cudaFuncAttributeMaxDynamicSharedMemorySize, GEMM_SMEM);
    cudaFuncSetAttribute(attn_mma, cudaFuncAttributeMaxDynamicSharedMemorySize, ATTN_SMEM);

    // 1) prep
    prep_merge<<<dim3(16, 8, 2), 256>>>(wq_w, wq_a, wq_b, wv_w, wv_a, wv_b, Wq, Wv);
    prep_split<<<3 * 8192, 256>>>(wk_w, wo_w, x, Wk, Wo, xh);

    // 2) fused QKV projection (fp16 1-term, 3-stage, 2 CTAs/SM)
    gemm16<1><<<dim3(D / 128, BSR / 128, 3), 256, GEMM_SMEM>>>(
        xh, nullptr, Wq, Wk, Wv, nullptr, Q, K, V, fc, fs);

    // 3) fp16 1-term MMA flash attention (BN=128, largest-first)
    attn_mma<<<dim3(SEQ / 128, NH, 4), 256, ATTN_SMEM>>>();

    // 4) output projection (fp16 2-term exact-O, fp32 out)
    gemm16<0><<<dim3(D / 128, BSR / 128, 1), 256, GEMM_SMEM>>>(
        Oh, Ol, Wo, nullptr, nullptr, out, nullptr, nullptr, nullptr, fc, fs);
}